// round 13
// baseline (speedup 1.0000x reference)
#include <cuda_runtime.h>

// HilbertSimulator: 4-qubit statevector sim, BATCH=2^21.
// Closed form (exact):
//   Ci  = cos(2*(x_i + w_i))
//   out = ( C1*C2*C3, C0*C1, C0*C1*C2, C0*C1*C2*C3 )
// Streaming 16B in + 16B out per element.
// TILES=2 sequential tiles per CTA -> grid=1024 (single resident wave,
// half the per-CTA fixed-cost churn).

#define TPB   256
#define EPT   4   // elements per thread per tile (front-batched LDG.128s)
#define TILES 2   // sequential tiles per CTA

__global__ void __launch_bounds__(TPB)
hilbert_kernel(const float4* __restrict__ x,
               const float*  __restrict__ w,
               float4*       __restrict__ out)
{
    // uniform weights (L2-broadcast)
    const float w0 = __ldg(w + 0);
    const float w1 = __ldg(w + 1);
    const float w2 = __ldg(w + 2);
    const float w3 = __ldg(w + 3);

    const int cta_base = blockIdx.x * (TPB * EPT * TILES) + threadIdx.x;

#pragma unroll 1
    for (int t = 0; t < TILES; t++) {
        const int base = cta_base + t * (TPB * EPT);

        // Front-batch 4 independent LDG.128s (warp-coalesced 128B lines).
        float4 xv[EPT];
#pragma unroll
        for (int e = 0; e < EPT; e++)
            xv[e] = x[base + e * TPB];

        float4 ov[EPT];
#pragma unroll
        for (int e = 0; e < EPT; e++) {
            const float C0 = __cosf(2.0f * (xv[e].x + w0));
            const float C1 = __cosf(2.0f * (xv[e].y + w1));
            const float C2 = __cosf(2.0f * (xv[e].z + w2));
            const float C3 = __cosf(2.0f * (xv[e].w + w3));

            const float t01 = C0 * C1;
            const float c23 = C2 * C3;

            ov[e] = make_float4(C1 * c23,     // <Z0>
                                t01,          // <Z1>
                                t01 * C2,     // <Z2>
                                t01 * c23);   // <Z3>
        }

#pragma unroll
        for (int e = 0; e < EPT; e++)
            out[base + e * TPB] = ov[e];
    }
}

extern "C" void kernel_launch(void* const* d_in, const int* in_sizes, int n_in,
                              void* d_out, int out_size)
{
    const float4* x = (const float4*)d_in[0];   // (BATCH, 4) float32
    const float*  w = (const float*)d_in[1];    // (1, 4) float32
    float4* out = (float4*)d_out;               // (BATCH, 4) float32

    const int n = in_sizes[0] / 4;              // BATCH = 2^21
    hilbert_kernel<<<n / (TPB * EPT * TILES), TPB>>>(x, w, out);
}

// round 14
// speedup vs baseline: 1.0520x; 1.0520x over previous
#include <cuda_runtime.h>
#include <cstdint>

// HilbertSimulator closed form:
//   Ci  = cos(2*(x_i + w_i))
//   out = ( C1*C2*C3, C0*C1, C0*C1*C2, C0*C1*C2*C3 )
// TMA-pipelined streaming: bulk G->S loads (mbarrier), compute in SMEM,
// bulk S->G stores. Bypasses the per-SM L1tex LDG wavefront queue that
// capped all LDG variants at ~3 TB/s.

#define TPB     256
#define TILE    512                 // elements per tile
#define TILE_B  (TILE * 16)         // 8192 bytes
#define NSTAGE  3                   // input stages
#define OSTAGE  2                   // output stages
#define GRID_MAX 740                // 5 CTAs/SM * 148 SMs

__device__ __forceinline__ uint32_t smem_u32(const void* p) {
    uint32_t a;
    asm("{ .reg .u64 t; cvta.to.shared.u64 t, %1; cvt.u32.u64 %0, t; }"
        : "=r"(a) : "l"(p));
    return a;
}

__device__ __forceinline__ void mbar_init(uint32_t mbar, uint32_t cnt) {
    asm volatile("mbarrier.init.shared.b64 [%0], %1;" :: "r"(mbar), "r"(cnt) : "memory");
}
__device__ __forceinline__ void mbar_expect_tx(uint32_t mbar, uint32_t bytes) {
    asm volatile("mbarrier.arrive.expect_tx.shared.b64 _, [%0], %1;"
                 :: "r"(mbar), "r"(bytes) : "memory");
}
__device__ __forceinline__ void mbar_wait(uint32_t mbar, uint32_t parity) {
    asm volatile(
        "{\n\t"
        ".reg .pred P1;\n\t"
        "WAIT_LOOP_%=:\n\t"
        "mbarrier.try_wait.parity.acquire.cta.shared::cta.b64 P1, [%0], %1, 0x989680;\n\t"
        "@P1 bra.uni WAIT_DONE_%=;\n\t"
        "bra.uni WAIT_LOOP_%=;\n\t"
        "WAIT_DONE_%=:\n\t"
        "}"
        :: "r"(mbar), "r"(parity) : "memory");
}
__device__ __forceinline__ void bulk_g2s(uint32_t dst_smem, const void* src, uint32_t bytes,
                                         uint32_t mbar) {
    asm volatile(
        "cp.async.bulk.shared::cluster.global.mbarrier::complete_tx::bytes [%0], [%1], %2, [%3];"
        :: "r"(dst_smem), "l"(src), "r"(bytes), "r"(mbar) : "memory");
}
__device__ __forceinline__ void bulk_s2g(void* dst, uint32_t src_smem, uint32_t bytes) {
    asm volatile("cp.async.bulk.global.shared::cta.bulk_group [%0], [%1], %2;"
                 :: "l"(dst), "r"(src_smem), "r"(bytes) : "memory");
}

__global__ void __launch_bounds__(TPB)
hilbert_tma_kernel(const float4* __restrict__ x,
                   const float*  __restrict__ w,
                   float4*       __restrict__ out,
                   int tiles_total)
{
    __shared__ float4 s_in[NSTAGE][TILE];    // 24 KB
    __shared__ float4 s_out[OSTAGE][TILE];   // 16 KB
    __shared__ uint64_t s_mbar[NSTAGE];

    const int tid  = threadIdx.x;
    const int bid  = blockIdx.x;
    const int grid = gridDim.x;

    const uint32_t in_base  = smem_u32(&s_in[0][0]);
    const uint32_t out_base = smem_u32(&s_out[0][0]);
    const uint32_t mb_base  = smem_u32(&s_mbar[0]);

    // uniform weights (L2-broadcast)
    const float w0 = __ldg(w + 0);
    const float w1 = __ldg(w + 1);
    const float w2 = __ldg(w + 2);
    const float w3 = __ldg(w + 3);

    const int n_my = (tiles_total - bid - 1) / grid + 1;   // bid < tiles_total

    if (tid == 0) {
        for (int s = 0; s < NSTAGE; s++) mbar_init(mb_base + 8 * s, 1);
    }
    __syncthreads();

    // Prologue: fill the pipeline
    if (tid == 0) {
        const int npro = n_my < NSTAGE ? n_my : NSTAGE;
        for (int p = 0; p < npro; p++) {
            const int T = bid + p * grid;
            mbar_expect_tx(mb_base + 8 * p, TILE_B);
            bulk_g2s(in_base + p * TILE_B, (const char*)x + (size_t)T * TILE_B,
                     TILE_B, mb_base + 8 * p);
        }
    }

#pragma unroll 1
    for (int it = 0; it < n_my; it++) {
        const int s  = it % NSTAGE;
        const int os = it & (OSTAGE - 1);
        const int T  = bid + it * grid;

        // wait for input tile (parity = use_count & 1)
        mbar_wait(mb_base + 8 * s, (uint32_t)((it / NSTAGE) & 1));

        // make sure the store that last used out-stage `os` has drained
        if (tid == 0)
            asm volatile("cp.async.bulk.wait_group.read 1;" ::: "memory");
        __syncthreads();

        // compute: 2 elements per thread
#pragma unroll
        for (int e = 0; e < 2; e++) {
            const int idx = tid + e * TPB;
            const float4 xv = s_in[s][idx];

            const float C0 = __cosf(2.0f * (xv.x + w0));
            const float C1 = __cosf(2.0f * (xv.y + w1));
            const float C2 = __cosf(2.0f * (xv.z + w2));
            const float C3 = __cosf(2.0f * (xv.w + w3));

            const float t01 = C0 * C1;
            const float c23 = C2 * C3;

            s_out[os][idx] = make_float4(C1 * c23, t01, t01 * C2, t01 * c23);
        }
        __syncthreads();   // all LDS from s_in[s] and STS to s_out[os] done

        if (tid == 0) {
            asm volatile("fence.proxy.async.shared::cta;" ::: "memory");
            bulk_s2g((char*)out + (size_t)T * TILE_B, out_base + os * TILE_B, TILE_B);
            asm volatile("cp.async.bulk.commit_group;" ::: "memory");

            // refill this input stage for tile it + NSTAGE
            const int itn = it + NSTAGE;
            if (itn < n_my) {
                const int Tn = bid + itn * grid;
                mbar_expect_tx(mb_base + 8 * s, TILE_B);
                bulk_g2s(in_base + s * TILE_B, (const char*)x + (size_t)Tn * TILE_B,
                         TILE_B, mb_base + 8 * s);
            }
        }
    }

    if (tid == 0)
        asm volatile("cp.async.bulk.wait_group 0;" ::: "memory");
}

extern "C" void kernel_launch(void* const* d_in, const int* in_sizes, int n_in,
                              void* d_out, int out_size)
{
    const float4* x = (const float4*)d_in[0];   // (BATCH, 4) float32
    const float*  w = (const float*)d_in[1];    // (1, 4) float32
    float4* out = (float4*)d_out;               // (BATCH, 4) float32

    const int n = in_sizes[0] / 4;              // BATCH = 2^21
    const int tiles = n / TILE;                 // 4096
    int grid = GRID_MAX;
    if (grid > tiles) grid = tiles;

    hilbert_tma_kernel<<<grid, TPB>>>(x, w, out, tiles);
}